// round 6
// baseline (speedup 1.0000x reference)
#include <cuda_runtime.h>
#include <cuda_fp16.h>
#include <cstdint>

#define NN   100000      // nodes
#define NPAD 100096      // 782 * 128
#define NE   1600000     // edges
#define H    128
#define NG   2000        // graphs
#define NS   200         // sets
#define NC   10          // classes
#define NBLK 98          // ceil(NN/1024) scan blocks
#define GPB  8           // graphs per block in k_psi

// ---------------- scratch (static device globals; no allocation) -------------
__device__ __align__(16) int   g_cnt [NN];
__device__ __align__(16) int   g_tmp [NN];
__device__ __align__(16) int   g_bsum[128];
__device__ __align__(16) int   g_row [NN + 1];
__device__ __align__(16) int   g_cur [NN];
__device__ __align__(16) int   g_csrc[NE];
__device__ __align__(16) float g_dinv[NN];
__device__ __align__(16) float g_hW [(size_t)NPAD * H];   // dinv-scaled GEMM out
__device__ __align__(16) float g_acc[(size_t)NPAD * H];   // layer output
__device__ __align__(16) float g_gemb[NG * H];
__device__ __align__(16) float g_agg [NS * H];

// ---------------- CSR build ---------------------------------------------------
__global__ void k_zero_cnt() {
    int i = blockIdx.x * 256 + threadIdx.x;
    if (i < NN) g_cnt[i] = 0;
}
__global__ void k_cnt(const int* __restrict__ dst) {
    int e = blockIdx.x * 256 + threadIdx.x;
    if (e < NE) atomicAdd(&g_cnt[dst[e]], 1);
}
__global__ void k_dinv() {
    int i = blockIdx.x * 256 + threadIdx.x;
    if (i < NN) g_dinv[i] = rsqrtf((float)(g_cnt[i] + 1));   // +1 self loop
}
__global__ __launch_bounds__(1024) void k_scan1() {
    __shared__ int sh[1024];
    int i = blockIdx.x * 1024 + threadIdx.x;
    int v = (i < NN) ? g_cnt[i] : 0;
    sh[threadIdx.x] = v;
    __syncthreads();
#pragma unroll
    for (int off = 1; off < 1024; off <<= 1) {
        int t = (threadIdx.x >= off) ? sh[threadIdx.x - off] : 0;
        __syncthreads();
        sh[threadIdx.x] += t;
        __syncthreads();
    }
    if (i < NN) g_tmp[i] = sh[threadIdx.x];
    if (threadIdx.x == 1023) g_bsum[blockIdx.x] = sh[1023];
}
__global__ __launch_bounds__(128) void k_scan2() {
    __shared__ int sh[128];
    int t = threadIdx.x;
    int v = (t < NBLK) ? g_bsum[t] : 0;
    sh[t] = v;
    __syncthreads();
#pragma unroll
    for (int off = 1; off < 128; off <<= 1) {
        int u = (t >= off) ? sh[t - off] : 0;
        __syncthreads();
        sh[t] += u;
        __syncthreads();
    }
    if (t < NBLK) g_bsum[t] = sh[t] - v;    // exclusive
}
__global__ void k_scan3() {
    int i = blockIdx.x * 256 + threadIdx.x;
    if (i < NN) {
        int excl = g_tmp[i] - g_cnt[i] + g_bsum[i >> 10];
        g_row[i] = excl;
        g_cur[i] = excl;
    }
    if (i == 0) g_row[NN] = NE;
}
__global__ void k_bucket(const int* __restrict__ src, const int* __restrict__ dst) {
    int e = blockIdx.x * 256 + threadIdx.x;
    if (e >= NE) return;
    int pos = atomicAdd(&g_cur[dst[e]], 1);
    g_csrc[pos] = src[e];
}

// ---------------- tensor-core GEMM with fp16x3 split -------------------------
__device__ __forceinline__ void mma16816(float* d, uint32_t a0, uint32_t a1,
                                         uint32_t a2, uint32_t a3,
                                         uint32_t b0, uint32_t b1) {
    asm volatile(
        "mma.sync.aligned.m16n8k16.row.col.f32.f16.f16.f32 "
        "{%0,%1,%2,%3}, {%4,%5,%6,%7}, {%8,%9}, {%0,%1,%2,%3};"
        : "+f"(d[0]), "+f"(d[1]), "+f"(d[2]), "+f"(d[3])
        : "r"(a0), "r"(a1), "r"(a2), "r"(a3), "r"(b0), "r"(b1));
}
__device__ __forceinline__ void fsplit(float a, __half& h, __half& l) {
    h = __float2half_rn(a);
    l = __float2half_rn(a - __half2float(h));
}

#define BKP 40   // padded k-stride in halves

__global__ __launch_bounds__(256) void k_gemm_tc(const float* __restrict__ Ax,
                                                 const float* __restrict__ Bm,
                                                 int use_x, int nrows) {
    __shared__ __half Ah[128][BKP], Al[128][BKP];   // [row][k]
    __shared__ __half Bh[128][BKP], Bl[128][BKP];   // transposed: [n][k]
    const float* A = use_x ? Ax : (const float*)g_acc;

    const int tid  = threadIdx.x;
    const int lane = tid & 31;
    const int w    = tid >> 5;
    const int g    = lane >> 2;   // 0..7
    const int t    = lane & 3;    // 0..3
    const int wm   = w & 3;
    const int wn   = w >> 2;
    const int rowBase = blockIdx.x * 128;

    float d[2][8][4];
#pragma unroll
    for (int mt = 0; mt < 2; mt++)
#pragma unroll
        for (int nt = 0; nt < 8; nt++)
#pragma unroll
            for (int i = 0; i < 4; i++) d[mt][nt][i] = 0.f;

    for (int k0 = 0; k0 < 128; k0 += 32) {
        __syncthreads();
#pragma unroll
        for (int i = 0; i < 4; i++) {
            int id = tid + i * 256;
            int r  = id >> 3;
            int c4 = (id & 7) * 4;
            int gr = rowBase + r;
            float4 v = make_float4(0.f, 0.f, 0.f, 0.f);
            if (gr < nrows) v = *(const float4*)(A + (size_t)gr * H + k0 + c4);
            __half h0, l0, h1, l1, h2, l2, h3, l3;
            fsplit(v.x, h0, l0); fsplit(v.y, h1, l1);
            fsplit(v.z, h2, l2); fsplit(v.w, h3, l3);
            Ah[r][c4 + 0] = h0; Ah[r][c4 + 1] = h1; Ah[r][c4 + 2] = h2; Ah[r][c4 + 3] = h3;
            Al[r][c4 + 0] = l0; Al[r][c4 + 1] = l1; Al[r][c4 + 2] = l2; Al[r][c4 + 3] = l3;
        }
#pragma unroll
        for (int i = 0; i < 4; i++) {
            int id = tid + i * 256;
            int kk = id >> 5;
            int n4 = (id & 31) * 4;
            float4 v = *(const float4*)(Bm + (size_t)(k0 + kk) * H + n4);
            __half h, l;
            fsplit(v.x, h, l); Bh[n4 + 0][kk] = h; Bl[n4 + 0][kk] = l;
            fsplit(v.y, h, l); Bh[n4 + 1][kk] = h; Bl[n4 + 1][kk] = l;
            fsplit(v.z, h, l); Bh[n4 + 2][kk] = h; Bl[n4 + 2][kk] = l;
            fsplit(v.w, h, l); Bh[n4 + 3][kk] = h; Bl[n4 + 3][kk] = l;
        }
        __syncthreads();

#pragma unroll
        for (int kt = 0; kt < 2; kt++) {
            int ks = kt * 16;
            uint32_t bh0[8], bh1[8], bl0[8], bl1[8];
#pragma unroll
            for (int nt = 0; nt < 8; nt++) {
                int n = wn * 64 + nt * 8 + g;
                bh0[nt] = *(const uint32_t*)&Bh[n][ks + 2 * t];
                bh1[nt] = *(const uint32_t*)&Bh[n][ks + 2 * t + 8];
                bl0[nt] = *(const uint32_t*)&Bl[n][ks + 2 * t];
                bl1[nt] = *(const uint32_t*)&Bl[n][ks + 2 * t + 8];
            }
#pragma unroll
            for (int mt = 0; mt < 2; mt++) {
                int m = wm * 32 + mt * 16;
                uint32_t ah0 = *(const uint32_t*)&Ah[m + g][ks + 2 * t];
                uint32_t ah1 = *(const uint32_t*)&Ah[m + g + 8][ks + 2 * t];
                uint32_t ah2 = *(const uint32_t*)&Ah[m + g][ks + 2 * t + 8];
                uint32_t ah3 = *(const uint32_t*)&Ah[m + g + 8][ks + 2 * t + 8];
                uint32_t al0 = *(const uint32_t*)&Al[m + g][ks + 2 * t];
                uint32_t al1 = *(const uint32_t*)&Al[m + g + 8][ks + 2 * t];
                uint32_t al2 = *(const uint32_t*)&Al[m + g][ks + 2 * t + 8];
                uint32_t al3 = *(const uint32_t*)&Al[m + g + 8][ks + 2 * t + 8];
#pragma unroll
                for (int nt = 0; nt < 8; nt++) {
                    mma16816(d[mt][nt], al0, al1, al2, al3, bh0[nt], bh1[nt]);
                    mma16816(d[mt][nt], ah0, ah1, ah2, ah3, bl0[nt], bl1[nt]);
                    mma16816(d[mt][nt], ah0, ah1, ah2, ah3, bh0[nt], bh1[nt]);
                }
            }
        }
    }

#pragma unroll
    for (int mt = 0; mt < 2; mt++) {
        int r0 = rowBase + wm * 32 + mt * 16 + g;
        int r1 = r0 + 8;
        float di0 = (r0 < nrows) ? g_dinv[r0] : 0.f;
        float di1 = (r1 < nrows) ? g_dinv[r1] : 0.f;
#pragma unroll
        for (int nt = 0; nt < 8; nt++) {
            int c = wn * 64 + nt * 8 + 2 * t;
            if (r0 < nrows) {
                g_hW[(size_t)r0 * H + c]     = di0 * d[mt][nt][0];
                g_hW[(size_t)r0 * H + c + 1] = di0 * d[mt][nt][1];
            }
            if (r1 < nrows) {
                g_hW[(size_t)r1 * H + c]     = di1 * d[mt][nt][2];
                g_hW[(size_t)r1 * H + c + 1] = di1 * d[mt][nt][3];
            }
        }
    }
}

// ---------------- CSR gather (shuffle-index, high MLP) -----------------------
// acc[i] = relu(dinv[i]*(sum hS[src] + hS[i]) + b); warp/node, lane q: dims 4q..4q+3
__global__ __launch_bounds__(256) void k_gather(const float* __restrict__ b) {
    int idx = blockIdx.x * 256 + threadIdx.x;
    int i = idx >> 5;
    if (i >= NN) return;
    int q = idx & 31;

    int lo = __ldg(g_row + i);
    int hi = __ldg(g_row + i + 1);

    float4 acc = __ldg((const float4*)(g_hW + (size_t)i * H) + q);   // self loop

    for (int base = lo; base < hi; base += 32) {
        int cnt = hi - base;
        if (cnt > 32) cnt = 32;
        int myi = (q < cnt) ? __ldg(g_csrc + base + q) : 0;
        int k = 0;
        for (; k + 8 <= cnt; k += 8) {
            int s0 = __shfl_sync(0xffffffffu, myi, k);
            int s1 = __shfl_sync(0xffffffffu, myi, k + 1);
            int s2 = __shfl_sync(0xffffffffu, myi, k + 2);
            int s3 = __shfl_sync(0xffffffffu, myi, k + 3);
            int s4 = __shfl_sync(0xffffffffu, myi, k + 4);
            int s5 = __shfl_sync(0xffffffffu, myi, k + 5);
            int s6 = __shfl_sync(0xffffffffu, myi, k + 6);
            int s7 = __shfl_sync(0xffffffffu, myi, k + 7);
            float4 v0 = __ldg((const float4*)(g_hW + (size_t)s0 * H) + q);
            float4 v1 = __ldg((const float4*)(g_hW + (size_t)s1 * H) + q);
            float4 v2 = __ldg((const float4*)(g_hW + (size_t)s2 * H) + q);
            float4 v3 = __ldg((const float4*)(g_hW + (size_t)s3 * H) + q);
            float4 v4 = __ldg((const float4*)(g_hW + (size_t)s4 * H) + q);
            float4 v5 = __ldg((const float4*)(g_hW + (size_t)s5 * H) + q);
            float4 v6 = __ldg((const float4*)(g_hW + (size_t)s6 * H) + q);
            float4 v7 = __ldg((const float4*)(g_hW + (size_t)s7 * H) + q);
            acc.x += ((v0.x + v1.x) + (v2.x + v3.x)) + ((v4.x + v5.x) + (v6.x + v7.x));
            acc.y += ((v0.y + v1.y) + (v2.y + v3.y)) + ((v4.y + v5.y) + (v6.y + v7.y));
            acc.z += ((v0.z + v1.z) + (v2.z + v3.z)) + ((v4.z + v5.z) + (v6.z + v7.z));
            acc.w += ((v0.w + v1.w) + (v2.w + v3.w)) + ((v4.w + v5.w) + (v6.w + v7.w));
        }
        for (; k < cnt; k++) {
            int s = __shfl_sync(0xffffffffu, myi, k);
            float4 v = __ldg((const float4*)(g_hW + (size_t)s * H) + q);
            acc.x += v.x; acc.y += v.y; acc.z += v.z; acc.w += v.w;
        }
    }

    float di = __ldg(g_dinv + i);
    float4 bb = __ldg((const float4*)b + q);
    float4 r;
    r.x = fmaxf(fmaf(di, acc.x, bb.x), 0.f);
    r.y = fmaxf(fmaf(di, acc.y, bb.y), 0.f);
    r.z = fmaxf(fmaf(di, acc.z, bb.z), 0.f);
    r.w = fmaxf(fmaf(di, acc.w, bb.w), 0.f);
    *((float4*)(g_acc + (size_t)i * H) + q) = r;
}

// ---------------- mean pool per graph (batch is sorted) ----------------------
__device__ __forceinline__ int lower_bound_i(const int* a, int n, int v) {
    int lo = 0, hi = n;
    while (lo < hi) { int m = (lo + hi) >> 1; if (a[m] < v) lo = m + 1; else hi = m; }
    return lo;
}
__global__ void k_pool(const int* __restrict__ batch) {
    int g = blockIdx.x, d = threadIdx.x;
    __shared__ int lohi[2];
    if (d == 0) lohi[0] = lower_bound_i(batch, NN, g);
    if (d == 1) lohi[1] = lower_bound_i(batch, NN, g + 1);
    __syncthreads();
    int lo = lohi[0], hi = lohi[1];
    float s = 0.f;
    for (int i = lo; i < hi; i++) s += g_acc[(size_t)i * H + d];
    float c = (float)(hi - lo);
    g_gemb[g * H + d] = s / fmaxf(c, 1.f);
}

// ---------------- zero agg ----------------------------------------------------
__global__ void k_zero_agg() {
    int i = blockIdx.x * 256 + threadIdx.x;
    if (i < NS * H) g_agg[i] = 0.f;
}

// ---------------- DeepSets psi (8 graphs/block) + segment-sum ----------------
__global__ __launch_bounds__(128) void k_psi(const int* __restrict__ setb,
                      const float* __restrict__ W1, const float* __restrict__ b1,
                      const float* __restrict__ W2, const float* __restrict__ b2) {
    int g0 = blockIdx.x * GPB, d = threadIdx.x;
    __shared__ float v[GPB][H], t[GPB][H];
#pragma unroll
    for (int j = 0; j < GPB; j++) v[j][d] = g_gemb[(g0 + j) * H + d];
    __syncthreads();
    float s[GPB];
    float bb = b1[d];
#pragma unroll
    for (int j = 0; j < GPB; j++) s[j] = bb;
#pragma unroll 4
    for (int k = 0; k < H; k++) {
        float w = __ldg(W1 + k * H + d);
#pragma unroll
        for (int j = 0; j < GPB; j++) s[j] = fmaf(v[j][k], w, s[j]);
    }
#pragma unroll
    for (int j = 0; j < GPB; j++) t[j][d] = fmaxf(s[j], 0.f);
    __syncthreads();
    float b2d = b2[d];
#pragma unroll
    for (int j = 0; j < GPB; j++) s[j] = b2d;
#pragma unroll 4
    for (int k = 0; k < H; k++) {
        float w = __ldg(W2 + k * H + d);
#pragma unroll
        for (int j = 0; j < GPB; j++) s[j] = fmaf(t[j][k], w, s[j]);
    }
#pragma unroll
    for (int j = 0; j < GPB; j++)
        atomicAdd(&g_agg[__ldg(setb + g0 + j) * H + d], tanhf(s[j]));
}

// ---------------- phi head ----------------------------------------------------
__global__ void k_final(const float* __restrict__ W1, const float* __restrict__ b1,
                        const float* __restrict__ W2, const float* __restrict__ b2,
                        float* __restrict__ out) {
    int s = blockIdx.x, d = threadIdx.x;
    __shared__ float a[H], t[H];
    a[d] = g_agg[s * H + d];
    __syncthreads();
    float acc = b1[d];
#pragma unroll 8
    for (int k = 0; k < H; k++) acc += a[k] * W1[k * H + d];
    t[d] = fmaxf(acc, 0.f);
    __syncthreads();
    if (d < NC) {
        float o = b2[d];
#pragma unroll 8
        for (int k = 0; k < H; k++) o += t[k] * W2[k * NC + d];
        out[s * NC + d] = o;
    }
}

// ---------------- launch ------------------------------------------------------
extern "C" void kernel_launch(void* const* d_in, const int* in_sizes, int n_in,
                              void* d_out, int out_size) {
    const float* x     = (const float*)d_in[0];
    const int*   ei    = (const int*)  d_in[1];
    const int*   batch = (const int*)  d_in[2];
    const int*   setb  = (const int*)  d_in[3];
    const float* W1    = (const float*)d_in[4];
    const float* b1    = (const float*)d_in[5];
    const float* W2    = (const float*)d_in[6];
    const float* b2    = (const float*)d_in[7];
    const float* W3    = (const float*)d_in[8];
    const float* b3    = (const float*)d_in[9];
    const float* psiW1 = (const float*)d_in[10];
    const float* psib1 = (const float*)d_in[11];
    const float* psiW2 = (const float*)d_in[12];
    const float* psib2 = (const float*)d_in[13];
    const float* phiW1 = (const float*)d_in[14];
    const float* phib1 = (const float*)d_in[15];
    const float* phiW2 = (const float*)d_in[16];
    const float* phib2 = (const float*)d_in[17];
    float* out = (float*)d_out;

    const int* src = ei;          // edge_index[0]
    const int* dst = ei + NE;     // edge_index[1]

    // launch #4 is the ncu-profiled slot -> put k_gemm_tc there
    k_zero_cnt<<<(NN + 255) / 256, 256>>>();                       // 1
    k_cnt     <<<(NE + 255) / 256, 256>>>(dst);                    // 2
    k_dinv    <<<(NN + 255) / 256, 256>>>();                       // 3
    k_gemm_tc <<<NPAD / 128, 256>>>(x, W1, 1, NN);                 // 4 (profiled)
    k_scan1   <<<NBLK, 1024>>>();                                  // 5
    k_scan2   <<<1, 128>>>();                                      // 6
    k_scan3   <<<(NN + 255) / 256, 256>>>();                       // 7
    k_bucket  <<<(NE + 255) / 256, 256>>>(src, dst);               // 8

    k_gather  <<<(NN * 32 + 255) / 256, 256>>>(b1);                // layer 0 finish
    k_gemm_tc <<<NPAD / 128, 256>>>(x, W2, 0, NN);
    k_gather  <<<(NN * 32 + 255) / 256, 256>>>(b2);
    k_gemm_tc <<<NPAD / 128, 256>>>(x, W3, 0, NN);
    k_gather  <<<(NN * 32 + 255) / 256, 256>>>(b3);

    k_pool    <<<NG, H>>>(batch);
    k_zero_agg<<<(NS * H + 255) / 256, 256>>>();
    k_psi     <<<NG / GPB, H>>>(setb, psiW1, psib1, psiW2, psib2);
    k_final   <<<NS, H>>>(phiW1, phib1, phiW2, phib2, out);
}

// round 7
// speedup vs baseline: 1.4863x; 1.4863x over previous
#include <cuda_runtime.h>
#include <cuda_fp16.h>
#include <cstdint>

#define NN   100000      // nodes
#define NPAD 100096      // 782 * 128
#define NE   1600000     // edges
#define H    128
#define NG   2000        // graphs
#define NS   200         // sets
#define NC   10          // classes
#define NBLK 98          // ceil(NN/1024) scan blocks
#define GPB  8           // graphs per block in k_psi

// ---------------- scratch (static device globals; no allocation) -------------
__device__ __align__(16) int    g_cnt [NN];
__device__ __align__(16) int    g_tmp [NN];
__device__ __align__(16) int    g_bsum[128];
__device__ __align__(16) int    g_row [NN + 1];
__device__ __align__(16) int    g_cur [NN];
__device__ __align__(16) int    g_csrc[NE];
__device__ __align__(16) float  g_dinv[NN];
__device__ __align__(16) __half g_Bth[H * H];   // W^T hi-halves [n][k]
__device__ __align__(16) __half g_Btl[H * H];   // W^T lo-halves [n][k]
__device__ __align__(16) float  g_hW [(size_t)NPAD * H];   // raw GEMM out (A@W)
__device__ __align__(16) float  g_acc[(size_t)NPAD * H];   // layer output
__device__ __align__(16) float  g_gemb[NG * H];
__device__ __align__(16) float  g_agg [NS * H];

// ---------------- CSR build ---------------------------------------------------
__global__ void k_zero_cnt() {
    int i = blockIdx.x * 256 + threadIdx.x;
    if (i < NN) g_cnt[i] = 0;
}
__global__ void k_cnt(const int* __restrict__ dst) {
    int e = blockIdx.x * 256 + threadIdx.x;
    if (e < NE) atomicAdd(&g_cnt[dst[e]], 1);
}
__global__ __launch_bounds__(1024) void k_scan1() {
    __shared__ int sh[1024];
    int i = blockIdx.x * 1024 + threadIdx.x;
    int v = (i < NN) ? g_cnt[i] : 0;
    sh[threadIdx.x] = v;
    __syncthreads();
#pragma unroll
    for (int off = 1; off < 1024; off <<= 1) {
        int t = (threadIdx.x >= off) ? sh[threadIdx.x - off] : 0;
        __syncthreads();
        sh[threadIdx.x] += t;
        __syncthreads();
    }
    if (i < NN) g_tmp[i] = sh[threadIdx.x];
    if (threadIdx.x == 1023) g_bsum[blockIdx.x] = sh[1023];
}
__global__ __launch_bounds__(128) void k_scan2() {
    __shared__ int sh[128];
    int t = threadIdx.x;
    int v = (t < NBLK) ? g_bsum[t] : 0;
    sh[t] = v;
    __syncthreads();
#pragma unroll
    for (int off = 1; off < 128; off <<= 1) {
        int u = (t >= off) ? sh[t - off] : 0;
        __syncthreads();
        sh[t] += u;
        __syncthreads();
    }
    if (t < NBLK) g_bsum[t] = sh[t] - v;    // exclusive
}
__global__ void k_scan3() {
    int i = blockIdx.x * 256 + threadIdx.x;
    if (i < NN) {
        int c = g_cnt[i];
        int excl = g_tmp[i] - c + g_bsum[i >> 10];
        g_row[i] = excl;
        g_cur[i] = excl;
        g_dinv[i] = rsqrtf((float)(c + 1));   // +1 self loop
    }
    if (i == 0) g_row[NN] = NE;
}
__global__ void k_bucket(const int* __restrict__ src, const int* __restrict__ dst) {
    int e = blockIdx.x * 256 + threadIdx.x;
    if (e >= NE) return;
    int pos = atomicAdd(&g_cur[dst[e]], 1);
    g_csrc[pos] = src[e];
}

// ---------------- per-layer weight prep: split + transpose -------------------
__global__ void k_prep_B(const float* __restrict__ Bm) {
    int idx = blockIdx.x * 256 + threadIdx.x;   // 16384
    if (idx < H * H) {
        int k = idx >> 7, n = idx & 127;
        float v = Bm[idx];                      // Bm[k][n]
        __half h = __float2half_rn(v);
        __half l = __float2half_rn(v - __half2float(h));
        g_Bth[n * H + k] = h;
        g_Btl[n * H + k] = l;
    }
}

// ---------------- tensor-core GEMM, fp16x3 split, ldmatrix -------------------
__device__ __forceinline__ void mma16816(float* d, uint32_t a0, uint32_t a1,
                                         uint32_t a2, uint32_t a3,
                                         uint32_t b0, uint32_t b1) {
    asm volatile(
        "mma.sync.aligned.m16n8k16.row.col.f32.f16.f16.f32 "
        "{%0,%1,%2,%3}, {%4,%5,%6,%7}, {%8,%9}, {%0,%1,%2,%3};"
        : "+f"(d[0]), "+f"(d[1]), "+f"(d[2]), "+f"(d[3])
        : "r"(a0), "r"(a1), "r"(a2), "r"(a3), "r"(b0), "r"(b1));
}
__device__ __forceinline__ void ldmx4(uint32_t& r0, uint32_t& r1,
                                      uint32_t& r2, uint32_t& r3, const void* p) {
    uint32_t a = (uint32_t)__cvta_generic_to_shared(p);
    asm volatile("ldmatrix.sync.aligned.m8n8.x4.shared.b16 {%0,%1,%2,%3}, [%4];"
                 : "=r"(r0), "=r"(r1), "=r"(r2), "=r"(r3) : "r"(a));
}
__device__ __forceinline__ void fsplit(float a, __half& h, __half& l) {
    h = __float2half_rn(a);
    l = __float2half_rn(a - __half2float(h));
}

#define BKP 40   // padded k-stride (80B rows: 16B-aligned, ldmatrix conflict-free)

__global__ __launch_bounds__(256) void k_gemm_tc(const float* __restrict__ Ax,
                                                 int use_x, int nrows) {
    __shared__ __half Ah[128][BKP], Al[128][BKP];   // [row][k]
    __shared__ __half Bh[128][BKP], Bl[128][BKP];   // [n][k]
    const float* A = use_x ? Ax : (const float*)g_acc;

    const int tid  = threadIdx.x;
    const int lane = tid & 31;
    const int w    = tid >> 5;
    const int g    = lane >> 2;
    const int t    = lane & 3;
    const int wm   = w & 3;        // 4 warps along M
    const int wn   = w >> 2;       // 2 warps along N
    const int rowBase = blockIdx.x * 128;

    // ldmatrix per-lane row/col components
    const int aRow = (lane & 7) + ((lane >> 3) & 1) * 8;   // + m0
    const int aColSel = (lane >> 4) * 8;                   // + ks
    const int bRow = ((lane >> 4) << 3) + (lane & 7);      // + wn*64 + j*16
    const int bColSel = ((lane >> 3) & 1) * 8;             // + ks

    float d[2][8][4];
#pragma unroll
    for (int mt = 0; mt < 2; mt++)
#pragma unroll
        for (int nt = 0; nt < 8; nt++)
#pragma unroll
            for (int i = 0; i < 4; i++) d[mt][nt][i] = 0.f;

    for (int k0 = 0; k0 < 128; k0 += 32) {
        __syncthreads();
        // stage A chunk 128x32: fsplit, vectorized uint2 stores
#pragma unroll
        for (int i = 0; i < 4; i++) {
            int id = tid + i * 256;           // 1024 float4 items
            int r  = id >> 3;
            int c4 = (id & 7) * 4;
            int gr = rowBase + r;
            float4 v = make_float4(0.f, 0.f, 0.f, 0.f);
            if (gr < nrows) v = *(const float4*)(A + (size_t)gr * H + k0 + c4);
            __half2 hh[2], ll[2];
            __half h0, l0, h1, l1;
            fsplit(v.x, h0, l0); fsplit(v.y, h1, l1);
            hh[0] = __halves2half2(h0, h1); ll[0] = __halves2half2(l0, l1);
            fsplit(v.z, h0, l0); fsplit(v.w, h1, l1);
            hh[1] = __halves2half2(h0, h1); ll[1] = __halves2half2(l0, l1);
            *(uint2*)&Ah[r][c4] = *(uint2*)hh;
            *(uint2*)&Al[r][c4] = *(uint2*)ll;
        }
        // stage B chunk 128x32 from pre-split g_Bth/g_Btl: pure uint4 copies
#pragma unroll
        for (int i = 0; i < 2; i++) {
            int id = tid + i * 256;           // 512 items of 8 halves
            int n  = id >> 2;
            int c8 = (id & 3) * 8;
            *(uint4*)&Bh[n][c8] = *(const uint4*)(g_Bth + n * H + k0 + c8);
            *(uint4*)&Bl[n][c8] = *(const uint4*)(g_Btl + n * H + k0 + c8);
        }
        __syncthreads();

#pragma unroll
        for (int kt = 0; kt < 2; kt++) {
            int ks = kt * 16;
            uint32_t bh0[8], bh1[8], bl0[8], bl1[8];
#pragma unroll
            for (int j = 0; j < 4; j++) {     // each x4 covers nt=2j, 2j+1
                int br = wn * 64 + j * 16 + bRow;
                int bc = ks + bColSel;
                ldmx4(bh0[2 * j], bh1[2 * j], bh0[2 * j + 1], bh1[2 * j + 1], &Bh[br][bc]);
                ldmx4(bl0[2 * j], bl1[2 * j], bl0[2 * j + 1], bl1[2 * j + 1], &Bl[br][bc]);
            }
#pragma unroll
            for (int mt = 0; mt < 2; mt++) {
                int ar = wm * 32 + mt * 16 + aRow;
                int ac = ks + aColSel;
                uint32_t ah0, ah1, ah2, ah3, al0, al1, al2, al3;
                ldmx4(ah0, ah1, ah2, ah3, &Ah[ar][ac]);
                ldmx4(al0, al1, al2, al3, &Al[ar][ac]);
#pragma unroll
                for (int nt = 0; nt < 8; nt++) {
                    mma16816(d[mt][nt], al0, al1, al2, al3, bh0[nt], bh1[nt]);
                    mma16816(d[mt][nt], ah0, ah1, ah2, ah3, bl0[nt], bl1[nt]);
                    mma16816(d[mt][nt], ah0, ah1, ah2, ah3, bh0[nt], bh1[nt]);
                }
            }
        }
    }

    // epilogue: raw fp32 store (dinv applied in gather)
#pragma unroll
    for (int mt = 0; mt < 2; mt++) {
        int r0 = rowBase + wm * 32 + mt * 16 + g;
        int r1 = r0 + 8;
#pragma unroll
        for (int nt = 0; nt < 8; nt++) {
            int c = wn * 64 + nt * 8 + 2 * t;
            if (r0 < nrows)
                *(float2*)(g_hW + (size_t)r0 * H + c) = make_float2(d[mt][nt][0], d[mt][nt][1]);
            if (r1 < nrows)
                *(float2*)(g_hW + (size_t)r1 * H + c) = make_float2(d[mt][nt][2], d[mt][nt][3]);
        }
    }
}

// ---------------- CSR gather -------------------------------------------------
// acc[i] = relu(dinv[i]*(sum dinv[s]*hW[s] + dinv[i]*hW[i]) + b)
__global__ __launch_bounds__(256) void k_gather(const float* __restrict__ b) {
    int idx = blockIdx.x * 256 + threadIdx.x;
    int i = idx >> 5;
    if (i >= NN) return;
    int q = idx & 31;

    int lo = __ldg(g_row + i);
    int hi = __ldg(g_row + i + 1);
    float di = __ldg(g_dinv + i);

    float4 vs = __ldg((const float4*)(g_hW + (size_t)i * H) + q);   // self loop
    float4 acc = make_float4(di * vs.x, di * vs.y, di * vs.z, di * vs.w);

    int j = lo;
    for (; j + 4 <= hi; j += 4) {
        int s0 = __ldg(g_csrc + j);
        int s1 = __ldg(g_csrc + j + 1);
        int s2 = __ldg(g_csrc + j + 2);
        int s3 = __ldg(g_csrc + j + 3);
        float d0 = __ldg(g_dinv + s0);
        float d1 = __ldg(g_dinv + s1);
        float d2 = __ldg(g_dinv + s2);
        float d3 = __ldg(g_dinv + s3);
        float4 v0 = __ldg((const float4*)(g_hW + (size_t)s0 * H) + q);
        float4 v1 = __ldg((const float4*)(g_hW + (size_t)s1 * H) + q);
        float4 v2 = __ldg((const float4*)(g_hW + (size_t)s2 * H) + q);
        float4 v3 = __ldg((const float4*)(g_hW + (size_t)s3 * H) + q);
        acc.x += (fmaf(d0, v0.x, d1 * v1.x) + fmaf(d2, v2.x, d3 * v3.x));
        acc.y += (fmaf(d0, v0.y, d1 * v1.y) + fmaf(d2, v2.y, d3 * v3.y));
        acc.z += (fmaf(d0, v0.z, d1 * v1.z) + fmaf(d2, v2.z, d3 * v3.z));
        acc.w += (fmaf(d0, v0.w, d1 * v1.w) + fmaf(d2, v2.w, d3 * v3.w));
    }
    for (; j < hi; j++) {
        int s = __ldg(g_csrc + j);
        float ds = __ldg(g_dinv + s);
        float4 v = __ldg((const float4*)(g_hW + (size_t)s * H) + q);
        acc.x = fmaf(ds, v.x, acc.x); acc.y = fmaf(ds, v.y, acc.y);
        acc.z = fmaf(ds, v.z, acc.z); acc.w = fmaf(ds, v.w, acc.w);
    }

    float4 bb = __ldg((const float4*)b + q);
    float4 r;
    r.x = fmaxf(fmaf(di, acc.x, bb.x), 0.f);
    r.y = fmaxf(fmaf(di, acc.y, bb.y), 0.f);
    r.z = fmaxf(fmaf(di, acc.z, bb.z), 0.f);
    r.w = fmaxf(fmaf(di, acc.w, bb.w), 0.f);
    *((float4*)(g_acc + (size_t)i * H) + q) = r;
}

// ---------------- mean pool per graph (batch is sorted) ----------------------
__device__ __forceinline__ int lower_bound_i(const int* a, int n, int v) {
    int lo = 0, hi = n;
    while (lo < hi) { int m = (lo + hi) >> 1; if (a[m] < v) lo = m + 1; else hi = m; }
    return lo;
}
__global__ void k_pool(const int* __restrict__ batch) {
    int g = blockIdx.x, d = threadIdx.x;
    __shared__ int lohi[2];
    if (d == 0) lohi[0] = lower_bound_i(batch, NN, g);
    if (d == 1) lohi[1] = lower_bound_i(batch, NN, g + 1);
    __syncthreads();
    int lo = lohi[0], hi = lohi[1];
    float s = 0.f;
    for (int i = lo; i < hi; i++) s += g_acc[(size_t)i * H + d];
    float c = (float)(hi - lo);
    g_gemb[g * H + d] = s / fmaxf(c, 1.f);
}

// ---------------- zero agg ----------------------------------------------------
__global__ void k_zero_agg() {
    int i = blockIdx.x * 256 + threadIdx.x;
    if (i < NS * H) g_agg[i] = 0.f;
}

// ---------------- DeepSets psi (8 graphs/block) + segment-sum ----------------
__global__ __launch_bounds__(128) void k_psi(const int* __restrict__ setb,
                      const float* __restrict__ W1, const float* __restrict__ b1,
                      const float* __restrict__ W2, const float* __restrict__ b2) {
    int g0 = blockIdx.x * GPB, d = threadIdx.x;
    __shared__ float v[GPB][H], t[GPB][H];
#pragma unroll
    for (int j = 0; j < GPB; j++) v[j][d] = g_gemb[(g0 + j) * H + d];
    __syncthreads();
    float s[GPB];
    float bb = b1[d];
#pragma unroll
    for (int j = 0; j < GPB; j++) s[j] = bb;
#pragma unroll 4
    for (int k = 0; k < H; k++) {
        float w = __ldg(W1 + k * H + d);
#pragma unroll
        for (int j = 0; j < GPB; j++) s[j] = fmaf(v[j][k], w, s[j]);
    }
#pragma unroll
    for (int j = 0; j < GPB; j++) t[j][d] = fmaxf(s[j], 0.f);
    __syncthreads();
    float b2d = b2[d];
#pragma unroll
    for (int j = 0; j < GPB; j++) s[j] = b2d;
#pragma unroll 4
    for (int k = 0; k < H; k++) {
        float w = __ldg(W2 + k * H + d);
#pragma unroll
        for (int j = 0; j < GPB; j++) s[j] = fmaf(t[j][k], w, s[j]);
    }
#pragma unroll
    for (int j = 0; j < GPB; j++)
        atomicAdd(&g_agg[__ldg(setb + g0 + j) * H + d], tanhf(s[j]));
}

// ---------------- phi head ----------------------------------------------------
__global__ void k_final(const float* __restrict__ W1, const float* __restrict__ b1,
                        const float* __restrict__ W2, const float* __restrict__ b2,
                        float* __restrict__ out) {
    int s = blockIdx.x, d = threadIdx.x;
    __shared__ float a[H], t[H];
    a[d] = g_agg[s * H + d];
    __syncthreads();
    float acc = b1[d];
#pragma unroll 8
    for (int k = 0; k < H; k++) acc += a[k] * W1[k * H + d];
    t[d] = fmaxf(acc, 0.f);
    __syncthreads();
    if (d < NC) {
        float o = b2[d];
#pragma unroll 8
        for (int k = 0; k < H; k++) o += t[k] * W2[k * NC + d];
        out[s * NC + d] = o;
    }
}

// ---------------- launch ------------------------------------------------------
extern "C" void kernel_launch(void* const* d_in, const int* in_sizes, int n_in,
                              void* d_out, int out_size) {
    const float* x     = (const float*)d_in[0];
    const int*   ei    = (const int*)  d_in[1];
    const int*   batch = (const int*)  d_in[2];
    const int*   setb  = (const int*)  d_in[3];
    const float* W1    = (const float*)d_in[4];
    const float* b1    = (const float*)d_in[5];
    const float* W2    = (const float*)d_in[6];
    const float* b2    = (const float*)d_in[7];
    const float* W3    = (const float*)d_in[8];
    const float* b3    = (const float*)d_in[9];
    const float* psiW1 = (const float*)d_in[10];
    const float* psib1 = (const float*)d_in[11];
    const float* psiW2 = (const float*)d_in[12];
    const float* psib2 = (const float*)d_in[13];
    const float* phiW1 = (const float*)d_in[14];
    const float* phib1 = (const float*)d_in[15];
    const float* phiW2 = (const float*)d_in[16];
    const float* phib2 = (const float*)d_in[17];
    float* out = (float*)d_out;

    const int* src = ei;          // edge_index[0]
    const int* dst = ei + NE;     // edge_index[1]

    // launch #4 = ncu-profiled slot -> k_gemm_tc
    k_zero_cnt<<<(NN + 255) / 256, 256>>>();                 // 1
    k_cnt     <<<(NE + 255) / 256, 256>>>(dst);              // 2
    k_prep_B  <<<H * H / 256, 256>>>(W1);                    // 3
    k_gemm_tc <<<NPAD / 128, 256>>>(x, 1, NN);               // 4 (profiled)
    k_scan1   <<<NBLK, 1024>>>();                            // 5
    k_scan2   <<<1, 128>>>();                                // 6
    k_scan3   <<<(NN + 255) / 256, 256>>>();                 // 7
    k_bucket  <<<(NE + 255) / 256, 256>>>(src, dst);         // 8

    k_gather  <<<(NN * 32 + 255) / 256, 256>>>(b1);
    k_prep_B  <<<H * H / 256, 256>>>(W2);
    k_gemm_tc <<<NPAD / 128, 256>>>(x, 0, NN);
    k_gather  <<<(NN * 32 + 255) / 256, 256>>>(b2);
    k_prep_B  <<<H * H / 256, 256>>>(W3);
    k_gemm_tc <<<NPAD / 128, 256>>>(x, 0, NN);
    k_gather  <<<(NN * 32 + 255) / 256, 256>>>(b3);

    k_pool    <<<NG, H>>>(batch);
    k_zero_agg<<<(NS * H + 255) / 256, 256>>>();
    k_psi     <<<NG / GPB, H>>>(setb, psiW1, psib1, psiW2, psib2);
    k_final   <<<NS, H>>>(phiW1, phib1, phiW2, phib2, out);
}